// round 6
// baseline (speedup 1.0000x reference)
#include <cuda_runtime.h>
#include <cuda_fp16.h>

#define Bq   512
#define Tt   365
#define Ff   16
#define Hh   256
#define G4   1024
#define NC   128     // CTAs
#define BS   4       // batch rows per CTA
#define NT   512     // 2 k-halves x (4 gate cols x 4 batch)

#define NCH1 34      // layer-1 chunks (4+4 rows of 2KB)
#define NCH2 64      // layer-2 chunks (2+2 rows of 4KB)
#define NCHS (NCH1 + NCH2)   // 98 chunks per step
#define NSLOT 3      // ring depth
#define CHB  16384   // bytes per chunk (two 8KB halves)

typedef unsigned long long u64;

// ---------------------------------------------------------------------------
// fp16 weights (L2-resident), fp32 fused biases.
// g_w1: [272 rows][1024 halves]  (W_ih1 16 rows then W_hh1 256 rows)
// g_w2: [256 rows][2048 halves]  row k = 256 groups of [wa0..3, wb0..3]
// ---------------------------------------------------------------------------
__device__ __half g_w1[(Ff + Hh) * G4];
__device__ __half g_w2[Hh * 2 * G4];
__device__ float  g_b1[G4];
__device__ float  g_b2[G4];

__device__ __forceinline__ u64 fma2(u64 a, u64 b, u64 c) {
    u64 d; asm("fma.rn.f32x2 %0, %1, %2, %3;" : "=l"(d) : "l"(a), "l"(b), "l"(c)); return d;
}
__device__ __forceinline__ u64 cvt2(unsigned hw) {
    u64 r;
    asm("{\n\t"
        ".reg .b16 l, h;\n\t"
        ".reg .f32 f0, f1;\n\t"
        "mov.b32 {l, h}, %1;\n\t"
        "cvt.f32.f16 f0, l;\n\t"
        "cvt.f32.f16 f1, h;\n\t"
        "mov.b64 %0, {f0, f1};\n\t"
        "}" : "=l"(r) : "r"(hw));
    return r;
}
__device__ __forceinline__ float sigf(float x) { return 1.0f / (1.0f + __expf(-x)); }

__device__ __forceinline__ unsigned s2u(const void* p) {
    unsigned a;
    asm("{ .reg .u64 t; cvta.to.shared.u64 t, %1; cvt.u32.u64 %0, t; }" : "=r"(a) : "l"(p));
    return a;
}
__device__ __forceinline__ void mwait(unsigned mbar, unsigned parity) {
    asm volatile(
        "{\n\t.reg .pred P;\n\t"
        "WL_%=:\n\t"
        "mbarrier.try_wait.parity.acquire.cta.shared::cta.b64 P, [%0], %1, 0x989680;\n\t"
        "@P bra.uni WD_%=;\n\t"
        "bra.uni WL_%=;\n\t"
        "WD_%=:\n\t}"
        :: "r"(mbar), "r"(parity) : "memory");
}
__device__ __forceinline__ void marrive(unsigned mbar) {
    asm volatile("mbarrier.arrive.shared.b64 _, [%0];" :: "r"(mbar) : "memory");
}
__device__ __forceinline__ void mexpect(unsigned mbar, unsigned tx) {
    asm volatile("mbarrier.arrive.expect_tx.shared.b64 _, [%0], %1;" :: "r"(mbar), "r"(tx) : "memory");
}
__device__ __forceinline__ void minit(unsigned mbar, unsigned cnt) {
    asm volatile("mbarrier.init.shared.b64 [%0], %1;" :: "r"(mbar), "r"(cnt) : "memory");
}
__device__ __forceinline__ void bulk(unsigned dst, const void* src, unsigned bytes, unsigned mbar) {
    asm volatile(
        "cp.async.bulk.shared::cluster.global.mbarrier::complete_tx::bytes [%0], [%1], %2, [%3];"
        :: "r"(dst), "l"(src), "r"(bytes), "r"(mbar) : "memory");
}

// ---------------------------------------------------------------------------
__global__ void prep_kernel(const float* __restrict__ wih1, const float* __restrict__ whh1,
                            const float* __restrict__ bih1, const float* __restrict__ bhh1,
                            const float* __restrict__ wih2, const float* __restrict__ whh2,
                            const float* __restrict__ bih2, const float* __restrict__ bhh2) {
    int idx = blockIdx.x * blockDim.x + threadIdx.x;
    if (idx < Hh * 2 * G4) {
        int k = idx >> 11, r = idx & 2047;
        int grp = r >> 3, q = r & 7;
        float v;
        if (q < 4) { int col = grp * 4 + q;       v = wih2[col * Hh + k]; }
        else       { int col = grp * 4 + (q - 4); v = whh2[col * Hh + k]; }
        g_w2[idx] = __float2half_rn(v);
    }
    if (idx < (Ff + Hh) * G4) {
        int k = idx >> 10, col = idx & 1023;
        float v = (k < Ff) ? wih1[col * Ff + k] : whh1[col * Hh + (k - Ff)];
        g_w1[idx] = __float2half_rn(v);
    }
    if (idx < G4) {
        g_b1[idx] = bih1[idx] + bhh1[idx];
        g_b2[idx] = bih2[idx] + bhh2[idx];
    }
}

// ---------------------------------------------------------------------------
// Producer (tid 0): issues chunk pcc; chunk = 2 x 8KB TMA bulk copies.
// Layer-1 chunk c: kh0 rows 4c..4c+3, kh1 rows 136+4c..+3 (of g_w1, 2KB rows).
// Layer-2 chunk c: kh0 rows 2c..2c+1, kh1 rows 128+2c..+1 (of g_w2, 4KB rows).
// ---------------------------------------------------------------------------
__device__ __forceinline__ void issue_chunk(int pcc, unsigned wb_u32, unsigned mb_u32) {
    int slot = pcc % NSLOT;
    unsigned epar = (unsigned)(((pcc / NSLOT) + 1) & 1);
    unsigned fmb = mb_u32 + slot * 8;
    unsigned emb = mb_u32 + NSLOT * 8 + slot * 8;
    mwait(emb, epar);
    int sc = pcc % NCHS;
    const __half *s0, *s1;
    if (sc < NCH1) {
        s0 = &g_w1[(4 * sc) * G4];
        s1 = &g_w1[(136 + 4 * sc) * G4];
    } else {
        int c2 = sc - NCH1;
        s0 = &g_w2[(size_t)(2 * c2) * 2048];
        s1 = &g_w2[(size_t)(128 + 2 * c2) * 2048];
    }
    unsigned d0 = wb_u32 + slot * CHB;
    mexpect(fmb, CHB);
    bulk(d0, s0, 8192, fmb);
    bulk(d0 + 8192, s1, 8192, fmb);
}

// ---------------------------------------------------------------------------
__global__ void __launch_bounds__(NT, 1)
lstm_kernel(const float* __restrict__ x,
            const float* __restrict__ wlin, const float* __restrict__ blin,
            float* __restrict__ out) {
    __shared__ __align__(16) __half wbuf[NSLOT][CHB / 2];  // 48KB ring
    __shared__ float zsp[2][BS * G4];                      // 32KB
    __shared__ float h1d[Hh * 8];                          // 8KB
    __shared__ float h2d[Hh * 8];                          // 8KB
    __shared__ float xs[Ff * 8];
    __shared__ __align__(16) unsigned long long mbars[2 * NSLOT]; // full[3], empty[3]

    const int tid = threadIdx.x;
    const int ct  = tid & 255;
    const int kh  = tid >> 8;
    const int b0  = blockIdx.x * BS;
    const unsigned wb_u32 = s2u(&wbuf[0][0]);
    const unsigned mb_u32 = s2u(&mbars[0]);

    if (tid == 0) {
        #pragma unroll
        for (int s = 0; s < NSLOT; ++s) {
            minit(mb_u32 + s * 8, 1);                 // full: TMA tx only
            minit(mb_u32 + NSLOT * 8 + s * 8, 16);    // empty: 16 warp arrivals
        }
    }
    if (tid < Hh) {
        float4 z4 = make_float4(0.f, 0.f, 0.f, 0.f);
        *(float4*)&h1d[tid * 8]     = z4;  *(float4*)&h1d[tid * 8 + 4] = z4;
        *(float4*)&h2d[tid * 8]     = z4;  *(float4*)&h2d[tid * 8 + 4] = z4;
    }
    float c1[2] = {0.f, 0.f};
    float c2[2] = {0.f, 0.f};

    u64 b1lo = 0, b1hi = 0, b2lo = 0, b2hi = 0;
    if (kh == 0) {
        b1lo = *(const u64*)&g_b1[4 * ct];  b1hi = *(const u64*)&g_b1[4 * ct + 2];
        b2lo = *(const u64*)&g_b2[4 * ct];  b2hi = *(const u64*)&g_b2[4 * ct + 2];
    }
    __syncthreads();   // mbarriers initialized

    int scc = 0;       // consumer chunk counter (all threads)
    int pcc = 0;       // producer chunk counter (tid 0)
    const bool isw0 = ((tid & 31) == 0);

    for (int t = 0; t < Tt; ++t) {
        // ---- stage x_t duplicated ----
        if (tid < Ff * BS) {
            int b = tid >> 4, f = tid & 15;
            float v = __ldg(&x[((size_t)(b0 + b) * Tt + t) * Ff + f]);
            *(float2*)&xs[f * 8 + 2 * b] = make_float2(v, v);
        }
        __syncthreads();

        // ================= LAYER 1 gates (TMA-fed, k-split) =================
        {
            if (tid == 0) { issue_chunk(pcc, wb_u32, mb_u32); issue_chunk(pcc + 1, wb_u32, mb_u32);
                            issue_chunk(pcc + 2, wb_u32, mb_u32); pcc += 3; }
            u64 a00 = b1lo, a01 = b1lo, a02 = b1lo, a03 = b1lo;
            u64 a10 = b1hi, a11 = b1hi, a12 = b1hi, a13 = b1hi;
            for (int c = 0; c < NCH1; ++c) {
                int slot = scc % NSLOT;
                unsigned fpar = (unsigned)((scc / NSLOT) & 1);
                mwait(mb_u32 + slot * 8, fpar);
                const __half* wb = &wbuf[slot][kh * 4096];
                const int rbase = kh ? (136 + 4 * c) : (4 * c);
                #pragma unroll
                for (int j = 0; j < 4; ++j) {
                    const int r = rbase + j;
                    uint2 wv = *(const uint2*)&wb[j * G4 + 4 * ct];
                    u64 w0 = cvt2(wv.x), w1 = cvt2(wv.y);
                    const float* hp = (r < Ff) ? &xs[r * 8] : &h1d[(r - Ff) * 8];
                    ulonglong2 hA = *(const ulonglong2*)hp;
                    ulonglong2 hB = *(const ulonglong2*)(hp + 4);
                    a00 = fma2(w0, hA.x, a00); a01 = fma2(w0, hA.y, a01);
                    a02 = fma2(w0, hB.x, a02); a03 = fma2(w0, hB.y, a03);
                    a10 = fma2(w1, hA.x, a10); a11 = fma2(w1, hA.y, a11);
                    a12 = fma2(w1, hB.x, a12); a13 = fma2(w1, hB.y, a13);
                }
                if (isw0) marrive(mb_u32 + NSLOT * 8 + slot * 8);
                ++scc;
                if (tid == 0 && c + 3 < NCH1) { issue_chunk(pcc, wb_u32, mb_u32); ++pcc; }
            }
            float* zb = zsp[kh];
            *(ulonglong2*)&zb[0 * G4 + 4 * ct] = make_ulonglong2(a00, a10);
            *(ulonglong2*)&zb[1 * G4 + 4 * ct] = make_ulonglong2(a01, a11);
            *(ulonglong2*)&zb[2 * G4 + 4 * ct] = make_ulonglong2(a02, a12);
            *(ulonglong2*)&zb[3 * G4 + 4 * ct] = make_ulonglong2(a03, a13);
        }
        __syncthreads();

        // ================= LAYER 1 update =================
        {
            const int u = ct;
            float hv[2];
            #pragma unroll
            for (int j = 0; j < 2; ++j) {
                const int b = 2 * kh + j;
                const float* z0 = &zsp[0][b * G4 + u];
                const float* z1 = &zsp[1][b * G4 + u];
                float zi = z0[0]      + z1[0];
                float zf = z0[Hh]     + z1[Hh];
                float zg = z0[2 * Hh] + z1[2 * Hh];
                float zo = z0[3 * Hh] + z1[3 * Hh];
                c1[j] = sigf(zf) * c1[j] + sigf(zi) * tanhf(zg);
                hv[j] = sigf(zo) * tanhf(c1[j]);
            }
            *(float4*)&h1d[u * 8 + 4 * kh] = make_float4(hv[0], hv[0], hv[1], hv[1]);
        }
        __syncthreads();

        // ================= LAYER 2 gates (TMA-fed, k-split) =================
        {
            if (tid == 0) { issue_chunk(pcc, wb_u32, mb_u32); issue_chunk(pcc + 1, wb_u32, mb_u32);
                            issue_chunk(pcc + 2, wb_u32, mb_u32); pcc += 3; }
            u64 a00 = b2lo, a01 = b2lo, a02 = b2lo, a03 = b2lo;
            u64 a10 = b2hi, a11 = b2hi, a12 = b2hi, a13 = b2hi;
            for (int c = 0; c < NCH2; ++c) {
                int slot = scc % NSLOT;
                unsigned fpar = (unsigned)((scc / NSLOT) & 1);
                mwait(mb_u32 + slot * 8, fpar);
                const __half* wb = &wbuf[slot][kh * 4096];
                const int kbase = kh * 128 + 2 * c;
                #pragma unroll
                for (int j = 0; j < 2; ++j) {
                    const int k = kbase + j;
                    uint4 wv = *(const uint4*)&wb[j * 2048 + 8 * ct];
                    u64 wa0 = cvt2(wv.x), wa1 = cvt2(wv.y);
                    u64 wb0 = cvt2(wv.z), wb1 = cvt2(wv.w);
                    ulonglong2 hA1 = *(const ulonglong2*)&h1d[k * 8];
                    ulonglong2 hB1 = *(const ulonglong2*)&h1d[k * 8 + 4];
                    ulonglong2 hA2 = *(const ulonglong2*)&h2d[k * 8];
                    ulonglong2 hB2 = *(const ulonglong2*)&h2d[k * 8 + 4];
                    a00 = fma2(wa0, hA1.x, a00); a01 = fma2(wa0, hA1.y, a01);
                    a02 = fma2(wa0, hB1.x, a02); a03 = fma2(wa0, hB1.y, a03);
                    a10 = fma2(wa1, hA1.x, a10); a11 = fma2(wa1, hA1.y, a11);
                    a12 = fma2(wa1, hB1.x, a12); a13 = fma2(wa1, hB1.y, a13);
                    a00 = fma2(wb0, hA2.x, a00); a01 = fma2(wb0, hA2.y, a01);
                    a02 = fma2(wb0, hB2.x, a02); a03 = fma2(wb0, hB2.y, a03);
                    a10 = fma2(wb1, hA2.x, a10); a11 = fma2(wb1, hA2.y, a11);
                    a12 = fma2(wb1, hB2.x, a12); a13 = fma2(wb1, hB2.y, a13);
                }
                if (isw0) marrive(mb_u32 + NSLOT * 8 + slot * 8);
                ++scc;
                if (tid == 0 && c + 3 < NCH2) { issue_chunk(pcc, wb_u32, mb_u32); ++pcc; }
            }
            float* zb = zsp[kh];
            *(ulonglong2*)&zb[0 * G4 + 4 * ct] = make_ulonglong2(a00, a10);
            *(ulonglong2*)&zb[1 * G4 + 4 * ct] = make_ulonglong2(a01, a11);
            *(ulonglong2*)&zb[2 * G4 + 4 * ct] = make_ulonglong2(a02, a12);
            *(ulonglong2*)&zb[3 * G4 + 4 * ct] = make_ulonglong2(a03, a13);
        }
        __syncthreads();

        // ================= LAYER 2 update =================
        {
            const int u = ct;
            float hv[2];
            #pragma unroll
            for (int j = 0; j < 2; ++j) {
                const int b = 2 * kh + j;
                const float* z0 = &zsp[0][b * G4 + u];
                const float* z1 = &zsp[1][b * G4 + u];
                float zi = z0[0]      + z1[0];
                float zf = z0[Hh]     + z1[Hh];
                float zg = z0[2 * Hh] + z1[2 * Hh];
                float zo = z0[3 * Hh] + z1[3 * Hh];
                c2[j] = sigf(zf) * c2[j] + sigf(zi) * tanhf(zg);
                hv[j] = sigf(zo) * tanhf(c2[j]);
            }
            *(float4*)&h2d[u * 8 + 4 * kh] = make_float4(hv[0], hv[0], hv[1], hv[1]);
        }
        __syncthreads();
    }

    // ================= linear head =================
    if (tid < 32 * BS) {
        int b = tid >> 5, lane = tid & 31;
        float s = 0.f;
        #pragma unroll
        for (int k = lane; k < Hh; k += 32) s += h2d[k * 8 + 2 * b] * __ldg(&wlin[k]);
        #pragma unroll
        for (int off = 16; off; off >>= 1) s += __shfl_xor_sync(0xffffffffu, s, off);
        if (lane == 0) out[b0 + b] = s + blin[0];
    }
}

// ---------------------------------------------------------------------------
extern "C" void kernel_launch(void* const* d_in, const int* in_sizes, int n_in,
                              void* d_out, int out_size) {
    const float* x    = (const float*)d_in[0];
    const float* wih1 = (const float*)d_in[1];
    const float* whh1 = (const float*)d_in[2];
    const float* bih1 = (const float*)d_in[3];
    const float* bhh1 = (const float*)d_in[4];
    const float* wih2 = (const float*)d_in[5];
    const float* whh2 = (const float*)d_in[6];
    const float* bih2 = (const float*)d_in[7];
    const float* bhh2 = (const float*)d_in[8];
    const float* wlin = (const float*)d_in[9];
    const float* blin = (const float*)d_in[10];
    float* out = (float*)d_out;

    prep_kernel<<<(Hh * 2 * G4 + 255) / 256, 256>>>(wih1, whh1, bih1, bhh1,
                                                    wih2, whh2, bih2, bhh2);
    lstm_kernel<<<NC, NT>>>(x, wlin, blin, out);
}

// round 7
// speedup vs baseline: 1.6533x; 1.6533x over previous
#include <cuda_runtime.h>
#include <cuda_fp16.h>

#define Bq   512
#define Tt   365
#define Ff   16
#define Hh   256
#define G4   1024
#define NC   128     // CTAs
#define BS   4       // batch rows per CTA
#define NT   512     // 2 k-halves x (4 gate cols x 4 batch)
#define KS1  120     // layer-1 h-row split: kh0 = 16 x-rows + 120 h, kh1 = 136 h

typedef unsigned long long u64;

// ---------------------------------------------------------------------------
// fp16 weights (L2-resident), fp32 fused biases.
// g_w1: [272 rows][1024 halves]  (W_ih1 16 rows then W_hh1 256 rows)
// g_w2: [256 rows][2048 halves]  row k = 256 groups of [wa0..3, wb0..3]
// ---------------------------------------------------------------------------
__device__ __half g_w1[(Ff + Hh) * G4];
__device__ __half g_w2[Hh * 2 * G4];
__device__ float  g_b1[G4];
__device__ float  g_b2[G4];

__device__ __forceinline__ u64 fma2(u64 a, u64 b, u64 c) {
    u64 d; asm("fma.rn.f32x2 %0, %1, %2, %3;" : "=l"(d) : "l"(a), "l"(b), "l"(c)); return d;
}
__device__ __forceinline__ u64 cvt2(unsigned hw) {
    u64 r;
    asm("{\n\t"
        ".reg .b16 l, h;\n\t"
        ".reg .f32 f0, f1;\n\t"
        "mov.b32 {l, h}, %1;\n\t"
        "cvt.f32.f16 f0, l;\n\t"
        "cvt.f32.f16 f1, h;\n\t"
        "mov.b64 %0, {f0, f1};\n\t"
        "}" : "=l"(r) : "r"(hw));
    return r;
}
__device__ __forceinline__ float sigf(float x) { return 1.0f / (1.0f + __expf(-x)); }

// ---------------------------------------------------------------------------
__global__ void prep_kernel(const float* __restrict__ wih1, const float* __restrict__ whh1,
                            const float* __restrict__ bih1, const float* __restrict__ bhh1,
                            const float* __restrict__ wih2, const float* __restrict__ whh2,
                            const float* __restrict__ bih2, const float* __restrict__ bhh2) {
    int idx = blockIdx.x * blockDim.x + threadIdx.x;
    if (idx < Hh * 2 * G4) {
        int k = idx >> 11, r = idx & 2047;
        int grp = r >> 3, q = r & 7;
        float v;
        if (q < 4) { int col = grp * 4 + q;       v = wih2[col * Hh + k]; }
        else       { int col = grp * 4 + (q - 4); v = whh2[col * Hh + k]; }
        g_w2[idx] = __float2half_rn(v);
    }
    if (idx < (Ff + Hh) * G4) {
        int k = idx >> 10, col = idx & 1023;
        float v = (k < Ff) ? wih1[col * Ff + k] : whh1[col * Hh + (k - Ff)];
        g_w1[idx] = __float2half_rn(v);
    }
    if (idx < G4) {
        g_b1[idx] = bih1[idx] + bhh1[idx];
        g_b2[idx] = bih2[idx] + bhh2[idx];
    }
}

// ---------------------------------------------------------------------------
// R5 architecture (k-split, 4 cols x 4 batch, f32x2, state in SMEM) +
// register double-buffered weight prefetch, one block ahead.
// ---------------------------------------------------------------------------
__global__ void __launch_bounds__(NT, 1)
lstm_kernel(const float* __restrict__ x,
            const float* __restrict__ wlin, const float* __restrict__ blin,
            float* __restrict__ out) {
    __shared__ float zsp[2][BS * G4];
    __shared__ float h1d[Hh * 8];
    __shared__ float h2d[Hh * 8];
    __shared__ float xs[Ff * 8];

    const int tid = threadIdx.x;
    const int ct  = tid & 255;
    const int kh  = tid >> 8;
    const int b0  = blockIdx.x * BS;

    if (tid < Hh) {
        float4 z4 = make_float4(0.f, 0.f, 0.f, 0.f);
        *(float4*)&h1d[tid * 8]     = z4;  *(float4*)&h1d[tid * 8 + 4] = z4;
        *(float4*)&h2d[tid * 8]     = z4;  *(float4*)&h2d[tid * 8 + 4] = z4;
    }
    float c1[2] = {0.f, 0.f};
    float c2[2] = {0.f, 0.f};

    u64 b1lo = 0, b1hi = 0, b2lo = 0, b2hi = 0;
    if (kh == 0) {
        b1lo = *(const u64*)&g_b1[4 * ct];  b1hi = *(const u64*)&g_b1[4 * ct + 2];
        b2lo = *(const u64*)&g_b2[4 * ct];  b2hi = *(const u64*)&g_b2[4 * ct + 2];
    }

    const __half* w1p = &g_w1[4 * ct];
    const __half* w2p = &g_w2[8 * ct];
    const __half* w1h = w1p + Ff * G4;            // h-rows of layer 1
    const int kbeg1 = kh ? KS1 : 0;
    const int kend1 = kh ? Hh : KS1;
    const int kbeg2 = kh * 128;

    __syncthreads();

    for (int t = 0; t < Tt; ++t) {
        // ---- stage x_t duplicated ----
        if (tid < Ff * BS) {
            int b = tid >> 4, f = tid & 15;
            float v = __ldg(&x[((size_t)(b0 + b) * Tt + t) * Ff + f]);
            *(float2*)&xs[f * 8 + 2 * b] = make_float2(v, v);
        }
        __syncthreads();

        // ================= LAYER 1 gates (k-split, prefetched) =================
        {
            u64 a00 = b1lo, a01 = b1lo, a02 = b1lo, a03 = b1lo;
            u64 a10 = b1hi, a11 = b1hi, a12 = b1hi, a13 = b1hi;

            auto blk1 = [&](int kb, const uint2* wv) {
                #pragma unroll
                for (int j = 0; j < 8; ++j) {
                    u64 w0 = cvt2(wv[j].x), w1 = cvt2(wv[j].y);
                    const float* hp = &h1d[(kb + j) * 8];
                    ulonglong2 hA = *(const ulonglong2*)hp;
                    ulonglong2 hB = *(const ulonglong2*)(hp + 4);
                    a00 = fma2(w0, hA.x, a00); a01 = fma2(w0, hA.y, a01);
                    a02 = fma2(w0, hB.x, a02); a03 = fma2(w0, hB.y, a03);
                    a10 = fma2(w1, hA.x, a10); a11 = fma2(w1, hA.y, a11);
                    a12 = fma2(w1, hB.x, a12); a13 = fma2(w1, hB.y, a13);
                }
            };

            // prologue: prefetch first h-block (covers latency under x-part too)
            uint2 wc[8];
            #pragma unroll
            for (int j = 0; j < 8; ++j)
                wc[j] = __ldg((const uint2*)(w1h + (size_t)(kbeg1 + j) * G4));

            if (kh == 0) {
                // x-part (16 rows) with its own 2-deep prefetch of 8-row blocks
                uint2 xw[8];
                #pragma unroll
                for (int j = 0; j < 8; ++j)
                    xw[j] = __ldg((const uint2*)(w1p + (size_t)j * G4));
                uint2 xw2[8];
                #pragma unroll
                for (int j = 0; j < 8; ++j)
                    xw2[j] = __ldg((const uint2*)(w1p + (size_t)(8 + j) * G4));
                #pragma unroll
                for (int j = 0; j < 8; ++j) {
                    u64 w0 = cvt2(xw[j].x), w1 = cvt2(xw[j].y);
                    const float* hp = &xs[j * 8];
                    ulonglong2 hA = *(const ulonglong2*)hp;
                    ulonglong2 hB = *(const ulonglong2*)(hp + 4);
                    a00 = fma2(w0, hA.x, a00); a01 = fma2(w0, hA.y, a01);
                    a02 = fma2(w0, hB.x, a02); a03 = fma2(w0, hB.y, a03);
                    a10 = fma2(w1, hA.x, a10); a11 = fma2(w1, hA.y, a11);
                    a12 = fma2(w1, hB.x, a12); a13 = fma2(w1, hB.y, a13);
                }
                #pragma unroll
                for (int j = 0; j < 8; ++j) {
                    u64 w0 = cvt2(xw2[j].x), w1 = cvt2(xw2[j].y);
                    const float* hp = &xs[(8 + j) * 8];
                    ulonglong2 hA = *(const ulonglong2*)hp;
                    ulonglong2 hB = *(const ulonglong2*)(hp + 4);
                    a00 = fma2(w0, hA.x, a00); a01 = fma2(w0, hA.y, a01);
                    a02 = fma2(w0, hB.x, a02); a03 = fma2(w0, hB.y, a03);
                    a10 = fma2(w1, hA.x, a10); a11 = fma2(w1, hA.y, a11);
                    a12 = fma2(w1, hB.x, a12); a13 = fma2(w1, hB.y, a13);
                }
            }

            // main h loop: load block kb+8 while computing block kb
            int kb = kbeg1;
            for (; kb + 8 < kend1; kb += 8) {
                uint2 wn[8];
                #pragma unroll
                for (int j = 0; j < 8; ++j)
                    wn[j] = __ldg((const uint2*)(w1h + (size_t)(kb + 8 + j) * G4));
                blk1(kb, wc);
                #pragma unroll
                for (int j = 0; j < 8; ++j) wc[j] = wn[j];
            }
            blk1(kb, wc);

            float* zb = zsp[kh];
            *(ulonglong2*)&zb[0 * G4 + 4 * ct] = make_ulonglong2(a00, a10);
            *(ulonglong2*)&zb[1 * G4 + 4 * ct] = make_ulonglong2(a01, a11);
            *(ulonglong2*)&zb[2 * G4 + 4 * ct] = make_ulonglong2(a02, a12);
            *(ulonglong2*)&zb[3 * G4 + 4 * ct] = make_ulonglong2(a03, a13);
        }
        __syncthreads();

        // ================= LAYER 1 update =================
        {
            const int u = ct;
            float hv[2];
            #pragma unroll
            for (int j = 0; j < 2; ++j) {
                const int b = 2 * kh + j;
                const float* z0 = &zsp[0][b * G4 + u];
                const float* z1 = &zsp[1][b * G4 + u];
                float zi = z0[0]      + z1[0];
                float zf = z0[Hh]     + z1[Hh];
                float zg = z0[2 * Hh] + z1[2 * Hh];
                float zo = z0[3 * Hh] + z1[3 * Hh];
                c1[j] = sigf(zf) * c1[j] + sigf(zi) * tanhf(zg);
                hv[j] = sigf(zo) * tanhf(c1[j]);
            }
            *(float4*)&h1d[u * 8 + 4 * kh] = make_float4(hv[0], hv[0], hv[1], hv[1]);
        }
        __syncthreads();

        // ================= LAYER 2 gates (k-split, prefetched) =================
        {
            u64 a00 = b2lo, a01 = b2lo, a02 = b2lo, a03 = b2lo;
            u64 a10 = b2hi, a11 = b2hi, a12 = b2hi, a13 = b2hi;

            auto blk2 = [&](int kb, const uint4* wv) {
                #pragma unroll
                for (int j = 0; j < 4; ++j) {
                    const int k = kb + j;
                    u64 wa0 = cvt2(wv[j].x), wa1 = cvt2(wv[j].y);
                    u64 wb0 = cvt2(wv[j].z), wb1 = cvt2(wv[j].w);
                    ulonglong2 hA1 = *(const ulonglong2*)&h1d[k * 8];
                    ulonglong2 hB1 = *(const ulonglong2*)&h1d[k * 8 + 4];
                    ulonglong2 hA2 = *(const ulonglong2*)&h2d[k * 8];
                    ulonglong2 hB2 = *(const ulonglong2*)&h2d[k * 8 + 4];
                    a00 = fma2(wa0, hA1.x, a00); a01 = fma2(wa0, hA1.y, a01);
                    a02 = fma2(wa0, hB1.x, a02); a03 = fma2(wa0, hB1.y, a03);
                    a10 = fma2(wa1, hA1.x, a10); a11 = fma2(wa1, hA1.y, a11);
                    a12 = fma2(wa1, hB1.x, a12); a13 = fma2(wa1, hB1.y, a13);
                    a00 = fma2(wb0, hA2.x, a00); a01 = fma2(wb0, hA2.y, a01);
                    a02 = fma2(wb0, hB2.x, a02); a03 = fma2(wb0, hB2.y, a03);
                    a10 = fma2(wb1, hA2.x, a10); a11 = fma2(wb1, hA2.y, a11);
                    a12 = fma2(wb1, hB2.x, a12); a13 = fma2(wb1, hB2.y, a13);
                }
            };

            uint4 wc[4];
            #pragma unroll
            for (int j = 0; j < 4; ++j)
                wc[j] = __ldg((const uint4*)(w2p + (size_t)(kbeg2 + j) * 2 * G4));

            int kb = kbeg2;
            const int kend2 = kbeg2 + 128;
            for (; kb + 4 < kend2; kb += 4) {
                uint4 wn[4];
                #pragma unroll
                for (int j = 0; j < 4; ++j)
                    wn[j] = __ldg((const uint4*)(w2p + (size_t)(kb + 4 + j) * 2 * G4));
                blk2(kb, wc);
                #pragma unroll
                for (int j = 0; j < 4; ++j) wc[j] = wn[j];
            }
            blk2(kb, wc);

            float* zb = zsp[kh];
            *(ulonglong2*)&zb[0 * G4 + 4 * ct] = make_ulonglong2(a00, a10);
            *(ulonglong2*)&zb[1 * G4 + 4 * ct] = make_ulonglong2(a01, a11);
            *(ulonglong2*)&zb[2 * G4 + 4 * ct] = make_ulonglong2(a02, a12);
            *(ulonglong2*)&zb[3 * G4 + 4 * ct] = make_ulonglong2(a03, a13);
        }
        __syncthreads();

        // ================= LAYER 2 update =================
        {
            const int u = ct;
            float hv[2];
            #pragma unroll
            for (int j = 0; j < 2; ++j) {
                const int b = 2 * kh + j;
                const float* z0 = &zsp[0][b * G4 + u];
                const float* z1 = &zsp[1][b * G4 + u];
                float zi = z0[0]      + z1[0];
                float zf = z0[Hh]     + z1[Hh];
                float zg = z0[2 * Hh] + z1[2 * Hh];
                float zo = z0[3 * Hh] + z1[3 * Hh];
                c2[j] = sigf(zf) * c2[j] + sigf(zi) * tanhf(zg);
                hv[j] = sigf(zo) * tanhf(c2[j]);
            }
            *(float4*)&h2d[u * 8 + 4 * kh] = make_float4(hv[0], hv[0], hv[1], hv[1]);
        }
        __syncthreads();
    }

    // ================= linear head =================
    if (tid < 32 * BS) {
        int b = tid >> 5, lane = tid & 31;
        float s = 0.f;
        #pragma unroll
        for (int k = lane; k < Hh; k += 32) s += h2d[k * 8 + 2 * b] * __ldg(&wlin[k]);
        #pragma unroll
        for (int off = 16; off; off >>= 1) s += __shfl_xor_sync(0xffffffffu, s, off);
        if (lane == 0) out[b0 + b] = s + blin[0];
    }
}

// ---------------------------------------------------------------------------
extern "C" void kernel_launch(void* const* d_in, const int* in_sizes, int n_in,
                              void* d_out, int out_size) {
    const float* x    = (const float*)d_in[0];
    const float* wih1 = (const float*)d_in[1];
    const float* whh1 = (const float*)d_in[2];
    const float* bih1 = (const float*)d_in[3];
    const float* bhh1 = (const float*)d_in[4];
    const float* wih2 = (const float*)d_in[5];
    const float* whh2 = (const float*)d_in[6];
    const float* bih2 = (const float*)d_in[7];
    const float* bhh2 = (const float*)d_in[8];
    const float* wlin = (const float*)d_in[9];
    const float* blin = (const float*)d_in[10];
    float* out = (float*)d_out;

    prep_kernel<<<(Hh * 2 * G4 + 255) / 256, 256>>>(wih1, whh1, bih1, bhh1,
                                                    wih2, whh2, bih2, bhh2);
    lstm_kernel<<<NC, NT>>>(x, wlin, blin, out);
}